// round 7
// baseline (speedup 1.0000x reference)
#include <cuda_runtime.h>
#include <cuda_bf16.h>
#include <cstdint>

#define DI __device__ __forceinline__

// bitsandbytes FP4 codebook (sign = bit 3)
__constant__ float FP4_TAB[16] = {
     0.0f,  0.0052083333f,  0.6666667f,  1.0f,  0.3333333f,  0.5f,  0.1666667f,  0.25f,
    -0.0f, -0.0052083333f, -0.6666667f, -1.0f, -0.3333333f, -0.5f, -0.1666667f, -0.25f};

#define B_ 16384L
#define I_ 2048L
#define H_ 4096L
#define O_ 2048L

// scratch (alloc-free rule: __device__ globals). All values are exact bf16
// values stored in f32 (the reference computes on bf16 tensors upcast to f32).
__device__ float g_Xf[B_ * I_];
__device__ float g_W1f[H_ * I_];
__device__ float g_W2f[H_ * H_];
__device__ float g_W3f[O_ * H_];
__device__ float g_H1f[B_ * H_];
__device__ float g_H2f[B_ * H_];

DI float bf16v(float x) { return __bfloat162float(__float2bfloat16(x)); }

// ---------------------------------------------------------------------------
// Elementwise prep: produce f32 tensors holding exact bf16 values
// ---------------------------------------------------------------------------

__global__ void cast_kernel(const float* __restrict__ x, float* __restrict__ y) {
    long i4 = blockIdx.x * (long)blockDim.x + threadIdx.x;
    float4 v = reinterpret_cast<const float4*>(x)[i4];
    float4 o;
    o.x = bf16v(v.x); o.y = bf16v(v.y); o.z = bf16v(v.z); o.w = bf16v(v.w);
    reinterpret_cast<float4*>(y)[i4] = o;
}

__global__ void dequant_kernel(const int* __restrict__ codes,
                               const float* __restrict__ absmax,
                               float* __restrict__ w) {
    long i4 = blockIdx.x * (long)blockDim.x + threadIdx.x;  // 4 elements per thread
    int4 c = reinterpret_cast<const int4*>(codes)[i4];
    float am = __ldg(&absmax[(i4 * 4) >> 6]);  // 4 consecutive elems share a 64-block
    float4 o;
    o.x = bf16v(FP4_TAB[c.x & 15] * am);
    o.y = bf16v(FP4_TAB[c.y & 15] * am);
    o.z = bf16v(FP4_TAB[c.z & 15] * am);
    o.w = bf16v(FP4_TAB[c.w & 15] * am);
    reinterpret_cast<float4*>(w)[i4] = o;
}

// ---------------------------------------------------------------------------
// Order-exact SGEMM: C[M,N] = relu?( bf16( bf16(seq_fma_acc) + bf16(bias) ) )
// Each output element is ONE sequential IEEE-FMA chain over k = 0..K-1
// ascending (register accumulator carried across all k-tiles) — replicating
// Eigen's gebp accumulation order (XLA CPU bf16 dot = f32 Eigen gemm).
// BM=BN=128, BK=16, 256 threads, 8x8 outputs/thread.
// ---------------------------------------------------------------------------

template <bool RELU>
__global__ void __launch_bounds__(256)
sgemm_seq(const float* __restrict__ A,   // [M,K] f32 (bf16 values)
          const float* __restrict__ W,   // [N,K] f32 (bf16 values)
          const float* __restrict__ bias,
          float* __restrict__ C,         // [M,N] f32 (bf16 values)
          int M, int N, int K) {
    constexpr int BM = 128, BN = 128, BK = 16;
    __shared__ float sA[BK][BM];
    __shared__ float sB[BK][BN];

    const int tid = threadIdx.x;
    const int tx = tid & 15;        // 0..15 -> col group
    const int ty = tid >> 4;        // 0..15 -> row group
    const int m0 = blockIdx.y * BM;
    const int n0 = blockIdx.x * BN;

    // gmem->smem staging: each thread owns one tile row half (8 floats)
    const int lr = tid >> 1;          // 0..127
    const int lc = (tid & 1) * 8;     // 0 or 8

    const float* gA = A + (size_t)(m0 + lr) * K + lc;
    const float* gW = W + (size_t)(n0 + lr) * K + lc;

    float acc[8][8];
#pragma unroll
    for (int i = 0; i < 8; i++)
#pragma unroll
        for (int j = 0; j < 8; j++) acc[i][j] = 0.f;

    float4 ra0 = *reinterpret_cast<const float4*>(gA);
    float4 ra1 = *reinterpret_cast<const float4*>(gA + 4);
    float4 rb0 = *reinterpret_cast<const float4*>(gW);
    float4 rb1 = *reinterpret_cast<const float4*>(gW + 4);

    const int KT = K / BK;
    for (int kt = 0; kt < KT; ++kt) {
        // store staged registers to smem, transposed to [k][m]/[k][n]
        sA[lc + 0][lr] = ra0.x; sA[lc + 1][lr] = ra0.y;
        sA[lc + 2][lr] = ra0.z; sA[lc + 3][lr] = ra0.w;
        sA[lc + 4][lr] = ra1.x; sA[lc + 5][lr] = ra1.y;
        sA[lc + 6][lr] = ra1.z; sA[lc + 7][lr] = ra1.w;
        sB[lc + 0][lr] = rb0.x; sB[lc + 1][lr] = rb0.y;
        sB[lc + 2][lr] = rb0.z; sB[lc + 3][lr] = rb0.w;
        sB[lc + 4][lr] = rb1.x; sB[lc + 5][lr] = rb1.y;
        sB[lc + 6][lr] = rb1.z; sB[lc + 7][lr] = rb1.w;
        __syncthreads();

        if (kt + 1 < KT) {  // prefetch next tile into registers
            gA += BK; gW += BK;
            ra0 = *reinterpret_cast<const float4*>(gA);
            ra1 = *reinterpret_cast<const float4*>(gA + 4);
            rb0 = *reinterpret_cast<const float4*>(gW);
            rb1 = *reinterpret_cast<const float4*>(gW + 4);
        }

#pragma unroll
        for (int k = 0; k < BK; k++) {   // ascending k — preserves chain order
            float a[8], b[8];
            *reinterpret_cast<float4*>(a)     = *reinterpret_cast<const float4*>(&sA[k][ty * 8]);
            *reinterpret_cast<float4*>(a + 4) = *reinterpret_cast<const float4*>(&sA[k][ty * 8 + 4]);
            *reinterpret_cast<float4*>(b)     = *reinterpret_cast<const float4*>(&sB[k][tx * 8]);
            *reinterpret_cast<float4*>(b + 4) = *reinterpret_cast<const float4*>(&sB[k][tx * 8 + 4]);
#pragma unroll
            for (int i = 0; i < 8; i++)
#pragma unroll
                for (int j = 0; j < 8; j++)
                    acc[i][j] = fmaf(a[i], b[j], acc[i][j]);
        }
        __syncthreads();
    }

    // Epilogue — reference rounding: bf16(matmul), + bf16(bias) in f32, bf16
    // round, relu. Output stored as f32 holding the exact bf16 value.
#pragma unroll
    for (int i = 0; i < 8; i++) {
        const int row = m0 + ty * 8 + i;
        float out[8];
#pragma unroll
        for (int j = 0; j < 8; j++) {
            const int col = n0 + tx * 8 + j;
            float v = bf16v(bf16v(acc[i][j]) + bf16v(bias[col]));
            if (RELU) v = fmaxf(v, 0.f);
            out[j] = v;
        }
        float* cp = &C[(size_t)row * N + n0 + tx * 8];
        *reinterpret_cast<float4*>(cp)     = *reinterpret_cast<float4*>(out);
        *reinterpret_cast<float4*>(cp + 4) = *reinterpret_cast<float4*>(out + 4);
    }
}

// ---------------------------------------------------------------------------

extern "C" void kernel_launch(void* const* d_in, const int* in_sizes, int n_in,
                              void* d_out, int out_size) {
    // Resolve inputs by element count (robust to metadata ordering).
    const float* x = nullptr;
    const int *codes1 = nullptr, *codes2 = nullptr, *codes3 = nullptr;
    const float *absmax1 = nullptr, *absmax2 = nullptr, *absmax3 = nullptr;
    const float *bias1 = nullptr, *bias2 = nullptr, *bias3 = nullptr;

    for (int i = 0; i < n_in; i++) {
        const long sz = in_sizes[i];
        const void* p = d_in[i];
        if (sz == B_ * I_) x = (const float*)p;
        else if (sz == H_ * H_) codes2 = (const int*)p;
        else if (sz == H_ * I_) { if (!codes1) codes1 = (const int*)p; else codes3 = (const int*)p; }
        else if (sz == (H_ * H_) / 64) absmax2 = (const float*)p;
        else if (sz == (H_ * I_) / 64) { if (!absmax1) absmax1 = (const float*)p; else absmax3 = (const float*)p; }
        else if (sz == H_) { if (!bias1) bias1 = (const float*)p; else bias2 = (const float*)p; }
        else if (sz == O_) bias3 = (const float*)p;
    }

    float *Xf, *W1, *W2, *W3, *H1, *H2;
    cudaGetSymbolAddress((void**)&Xf, g_Xf);
    cudaGetSymbolAddress((void**)&W1, g_W1f);
    cudaGetSymbolAddress((void**)&W2, g_W2f);
    cudaGetSymbolAddress((void**)&W3, g_W3f);
    cudaGetSymbolAddress((void**)&H1, g_H1f);
    cudaGetSymbolAddress((void**)&H2, g_H2f);

    // elementwise prep
    cast_kernel<<<(unsigned)((B_ * I_) / 4 / 256), 256>>>(x, Xf);
    dequant_kernel<<<(unsigned)((H_ * I_) / 4 / 256), 256>>>(codes1, absmax1, W1);
    dequant_kernel<<<(unsigned)((H_ * H_) / 4 / 256), 256>>>(codes2, absmax2, W2);
    dequant_kernel<<<(unsigned)((O_ * H_) / 4 / 256), 256>>>(codes3, absmax3, W3);

    // layer 1: [16384,2048] @ [4096,2048]^T -> relu -> H1
    sgemm_seq<true><<<dim3(H_ / 128, B_ / 128), 256>>>(
        Xf, W1, bias1, H1, (int)B_, (int)H_, (int)I_);
    // layer 2: [16384,4096] @ [4096,4096]^T -> relu -> H2
    sgemm_seq<true><<<dim3(H_ / 128, B_ / 128), 256>>>(
        H1, W2, bias2, H2, (int)B_, (int)H_, (int)H_);
    // layer 3: [16384,4096] @ [2048,4096]^T -> d_out (f32 = upcast bf16)
    sgemm_seq<false><<<dim3(O_ / 128, B_ / 128), 256>>>(
        H2, W3, bias3, (float*)d_out, (int)B_, (int)O_, (int)H_);
}

// round 8
// speedup vs baseline: 1.1093x; 1.1093x over previous
#include <cuda_runtime.h>
#include <cuda_bf16.h>
#include <cstdint>

#define DI __device__ __forceinline__

// bitsandbytes FP4 codebook (sign = bit 3)
__constant__ float FP4_TAB[16] = {
     0.0f,  0.0052083333f,  0.6666667f,  1.0f,  0.3333333f,  0.5f,  0.1666667f,  0.25f,
    -0.0f, -0.0052083333f, -0.6666667f, -1.0f, -0.3333333f, -0.5f, -0.1666667f, -0.25f};

#define B_ 16384L
#define I_ 2048L
#define H_ 4096L
#define O_ 2048L

// scratch (alloc-free rule: __device__ globals). All values are exact bf16
// values stored in f32 (the reference computes on bf16 tensors upcast to f32).
__device__ float g_Xf[B_ * I_];
__device__ float g_W1f[H_ * I_];
__device__ float g_W2f[H_ * H_];
__device__ float g_W3f[O_ * H_];
__device__ float g_H1f[B_ * H_];
__device__ float g_H2f[B_ * H_];

DI float bf16v(float x) { return __bfloat162float(__float2bfloat16(x)); }

// packed dual-FP32 FMA (Blackwell FFMA2). Per-lane IEEE RN fma — bit-identical
// to two scalar fmaf calls, so accumulation-order semantics are unchanged.
DI void fma2(uint64_t& d, uint64_t a, uint64_t b) {
    asm("fma.rn.f32x2 %0, %1, %2, %3;" : "=l"(d) : "l"(a), "l"(b), "l"(d));
}
DI uint64_t pack2(float lo, float hi) {
    uint64_t r;
    asm("mov.b64 %0, {%1, %2};" : "=l"(r) : "f"(lo), "f"(hi));
    return r;
}
DI void unpack2(float& lo, float& hi, uint64_t v) {
    asm("mov.b64 {%0, %1}, %2;" : "=f"(lo), "=f"(hi) : "l"(v));
}

// ---------------------------------------------------------------------------
// Elementwise prep: produce f32 tensors holding exact bf16 values
// ---------------------------------------------------------------------------

__global__ void cast_kernel(const float* __restrict__ x, float* __restrict__ y) {
    long i4 = blockIdx.x * (long)blockDim.x + threadIdx.x;
    float4 v = reinterpret_cast<const float4*>(x)[i4];
    float4 o;
    o.x = bf16v(v.x); o.y = bf16v(v.y); o.z = bf16v(v.z); o.w = bf16v(v.w);
    reinterpret_cast<float4*>(y)[i4] = o;
}

__global__ void dequant_kernel(const int* __restrict__ codes,
                               const float* __restrict__ absmax,
                               float* __restrict__ w) {
    long i4 = blockIdx.x * (long)blockDim.x + threadIdx.x;  // 4 elements per thread
    int4 c = reinterpret_cast<const int4*>(codes)[i4];
    float am = __ldg(&absmax[(i4 * 4) >> 6]);  // 4 consecutive elems share a 64-block
    float4 o;
    o.x = bf16v(FP4_TAB[c.x & 15] * am);
    o.y = bf16v(FP4_TAB[c.y & 15] * am);
    o.z = bf16v(FP4_TAB[c.z & 15] * am);
    o.w = bf16v(FP4_TAB[c.w & 15] * am);
    reinterpret_cast<float4*>(w)[i4] = o;
}

// ---------------------------------------------------------------------------
// Order-exact SGEMM on the FFMA2 (f32x2) pipe.
// C[M,N] = relu?( bf16( bf16(seq_fma_acc) + bf16(bias) ) )
// Each output element remains ONE sequential IEEE-FMA chain over k ascending
// (bit-identical to the scalar-fmaf R7 kernel, which passed at 5.4e-4).
// BM=BN=128, BK=16, 256 threads / 8 warps (2m x 4n), warp tile 64x32,
// lane grid 8x4 (broadcast-friendly), 8x8 outputs/thread, pairs along j.
// ---------------------------------------------------------------------------

template <bool RELU>
__global__ void __launch_bounds__(256)
sgemm_f32x2(const float* __restrict__ A,   // [M,K] f32 (bf16 values)
            const float* __restrict__ W,   // [N,K] f32 (bf16 values)
            const float* __restrict__ bias,
            float* __restrict__ C,         // [M,N] f32 (bf16 values)
            int M, int N, int K) {
    constexpr int BM = 128, BN = 128, BK = 16, LW = 132;  // 132: pad kills store conflicts
    __shared__ __align__(16) float sA[BK][LW];
    __shared__ __align__(16) float sB[BK][LW];

    const int tid  = threadIdx.x;
    const int lane = tid & 31;
    const int warp = tid >> 5;
    const int wm = (warp & 1) * 64;     // warp m offset
    const int wn = (warp >> 1) * 32;    // warp n offset
    const int lr = lane >> 2;           // 0..7  -> row group (8 rows each)
    const int lc = lane & 3;            // 0..3  -> col group (8 cols each)
    const int m0 = blockIdx.y * BM;
    const int n0 = blockIdx.x * BN;

    // gmem->smem staging: each thread owns one tile-row half (8 floats)
    const int sr = tid >> 1;            // 0..127
    const int sc = (tid & 1) * 8;       // 0 or 8

    const float* gA = A + (size_t)(m0 + sr) * K + sc;
    const float* gW = W + (size_t)(n0 + sr) * K + sc;

    uint64_t acc[8][4];
    const uint64_t z2 = pack2(0.f, 0.f);
#pragma unroll
    for (int i = 0; i < 8; i++)
#pragma unroll
        for (int j = 0; j < 4; j++) acc[i][j] = z2;

    float4 ra0 = *reinterpret_cast<const float4*>(gA);
    float4 ra1 = *reinterpret_cast<const float4*>(gA + 4);
    float4 rb0 = *reinterpret_cast<const float4*>(gW);
    float4 rb1 = *reinterpret_cast<const float4*>(gW + 4);

    const int KT = K / BK;
    for (int kt = 0; kt < KT; ++kt) {
        // staged registers -> smem, transposed to [k][m] / [k][n]
        sA[sc + 0][sr] = ra0.x; sA[sc + 1][sr] = ra0.y;
        sA[sc + 2][sr] = ra0.z; sA[sc + 3][sr] = ra0.w;
        sA[sc + 4][sr] = ra1.x; sA[sc + 5][sr] = ra1.y;
        sA[sc + 6][sr] = ra1.z; sA[sc + 7][sr] = ra1.w;
        sB[sc + 0][sr] = rb0.x; sB[sc + 1][sr] = rb0.y;
        sB[sc + 2][sr] = rb0.z; sB[sc + 3][sr] = rb0.w;
        sB[sc + 4][sr] = rb1.x; sB[sc + 5][sr] = rb1.y;
        sB[sc + 6][sr] = rb1.z; sB[sc + 7][sr] = rb1.w;
        __syncthreads();

        if (kt + 1 < KT) {  // prefetch next tile into registers
            gA += BK; gW += BK;
            ra0 = *reinterpret_cast<const float4*>(gA);
            ra1 = *reinterpret_cast<const float4*>(gA + 4);
            rb0 = *reinterpret_cast<const float4*>(gW);
            rb1 = *reinterpret_cast<const float4*>(gW + 4);
        }

#pragma unroll
        for (int k = 0; k < BK; k++) {   // ascending k — preserves chain order
            float a[8];
            *reinterpret_cast<float4*>(a)     = *reinterpret_cast<const float4*>(&sA[k][wm + lr * 8]);
            *reinterpret_cast<float4*>(a + 4) = *reinterpret_cast<const float4*>(&sA[k][wm + lr * 8 + 4]);
            uint64_t bp[4];   // b pairs straight from smem (LDS.64, 8B aligned)
            const uint64_t* bq = reinterpret_cast<const uint64_t*>(&sB[k][wn + lc * 8]);
            bp[0] = bq[0]; bp[1] = bq[1]; bp[2] = bq[2]; bp[3] = bq[3];
#pragma unroll
            for (int i = 0; i < 8; i++) {
                const uint64_t ad = pack2(a[i], a[i]);
#pragma unroll
                for (int j = 0; j < 4; j++)
                    fma2(acc[i][j], ad, bp[j]);
            }
        }
        __syncthreads();
    }

    // Epilogue — reference rounding: bf16(matmul), + bf16(bias) in f32, bf16
    // round, relu. Output stored as f32 holding the exact bf16 value.
    float bb[8];
#pragma unroll
    for (int j = 0; j < 8; j++) bb[j] = bf16v(bias[n0 + wn + lc * 8 + j]);

#pragma unroll
    for (int i = 0; i < 8; i++) {
        const int row = m0 + wm + lr * 8 + i;
        float out[8];
#pragma unroll
        for (int j = 0; j < 4; j++) {
            float v0, v1;
            unpack2(v0, v1, acc[i][j]);
            v0 = bf16v(bf16v(v0) + bb[2 * j]);
            v1 = bf16v(bf16v(v1) + bb[2 * j + 1]);
            if (RELU) { v0 = fmaxf(v0, 0.f); v1 = fmaxf(v1, 0.f); }
            out[2 * j] = v0; out[2 * j + 1] = v1;
        }
        float* cp = &C[(size_t)row * N + n0 + wn + lc * 8];
        *reinterpret_cast<float4*>(cp)     = *reinterpret_cast<float4*>(out);
        *reinterpret_cast<float4*>(cp + 4) = *reinterpret_cast<float4*>(out + 4);
    }
}

// ---------------------------------------------------------------------------

extern "C" void kernel_launch(void* const* d_in, const int* in_sizes, int n_in,
                              void* d_out, int out_size) {
    // Resolve inputs by element count (robust to metadata ordering).
    const float* x = nullptr;
    const int *codes1 = nullptr, *codes2 = nullptr, *codes3 = nullptr;
    const float *absmax1 = nullptr, *absmax2 = nullptr, *absmax3 = nullptr;
    const float *bias1 = nullptr, *bias2 = nullptr, *bias3 = nullptr;

    for (int i = 0; i < n_in; i++) {
        const long sz = in_sizes[i];
        const void* p = d_in[i];
        if (sz == B_ * I_) x = (const float*)p;
        else if (sz == H_ * H_) codes2 = (const int*)p;
        else if (sz == H_ * I_) { if (!codes1) codes1 = (const int*)p; else codes3 = (const int*)p; }
        else if (sz == (H_ * H_) / 64) absmax2 = (const float*)p;
        else if (sz == (H_ * I_) / 64) { if (!absmax1) absmax1 = (const float*)p; else absmax3 = (const float*)p; }
        else if (sz == H_) { if (!bias1) bias1 = (const float*)p; else bias2 = (const float*)p; }
        else if (sz == O_) bias3 = (const float*)p;
    }

    float *Xf, *W1, *W2, *W3, *H1, *H2;
    cudaGetSymbolAddress((void**)&Xf, g_Xf);
    cudaGetSymbolAddress((void**)&W1, g_W1f);
    cudaGetSymbolAddress((void**)&W2, g_W2f);
    cudaGetSymbolAddress((void**)&W3, g_W3f);
    cudaGetSymbolAddress((void**)&H1, g_H1f);
    cudaGetSymbolAddress((void**)&H2, g_H2f);

    // elementwise prep
    cast_kernel<<<(unsigned)((B_ * I_) / 4 / 256), 256>>>(x, Xf);
    dequant_kernel<<<(unsigned)((H_ * I_) / 4 / 256), 256>>>(codes1, absmax1, W1);
    dequant_kernel<<<(unsigned)((H_ * H_) / 4 / 256), 256>>>(codes2, absmax2, W2);
    dequant_kernel<<<(unsigned)((O_ * H_) / 4 / 256), 256>>>(codes3, absmax3, W3);

    // layer 1: [16384,2048] @ [4096,2048]^T -> relu -> H1
    sgemm_f32x2<true><<<dim3(H_ / 128, B_ / 128), 256>>>(
        Xf, W1, bias1, H1, (int)B_, (int)H_, (int)I_);
    // layer 2: [16384,4096] @ [4096,4096]^T -> relu -> H2
    sgemm_f32x2<true><<<dim3(H_ / 128, B_ / 128), 256>>>(
        H1, W2, bias2, H2, (int)B_, (int)H_, (int)H_);
    // layer 3: [16384,4096] @ [2048,4096]^T -> d_out (f32 = upcast bf16)
    sgemm_f32x2<false><<<dim3(O_ / 128, B_ / 128), 256>>>(
        H2, W3, bias3, (float*)d_out, (int)B_, (int)O_, (int)H_);
}